// round 5
// baseline (speedup 1.0000x reference)
#include <cuda_runtime.h>

#define IMG 512
#define TW 64
#define TH 32
#define KS 11
#define HALO 5
#define COLS 74              /* TW + 2*HALO */
#define S2 75                /* row stride (odd -> conflict-free) */
#define RG 4                 /* output rows per vertical task */
#define NTASK (COLS*(TH/RG)) /* 592 */
#define NTHREADS 256
#define NSLOTS 128
#define NBLK (8*16*64)
#define SMEM_BYTES (TH*S2*8*2 + TH*S2*4)   /* 48000 B -> 4 CTAs/SM */

typedef unsigned long long u64;

__device__ double g_slots[NSLOTS];   /* zero-init; last block re-zeros each replay */
__device__ unsigned int g_done = 0;

__device__ __forceinline__ u64 pack2(float x, float y) {
    u64 r; asm("mov.b64 %0, {%1,%2};" : "=l"(r) : "f"(x), "f"(y)); return r;
}
__device__ __forceinline__ void unpack2(u64 v, float& x, float& y) {
    asm("mov.b64 {%0,%1}, %2;" : "=f"(x), "=f"(y) : "l"(v));
}
__device__ __forceinline__ u64 fma2(u64 a, u64 b, u64 c) {
    u64 d; asm("fma.rn.f32x2 %0, %1, %2, %3;" : "=l"(d) : "l"(a), "l"(b), "l"(c)); return d;
}
__device__ __forceinline__ u64 mul2(u64 a, u64 b) {
    u64 d; asm("mul.rn.f32x2 %0, %1, %2;" : "=l"(d) : "l"(a), "l"(b)); return d;
}

/* Gaussian symmetry w[k] == w[10-k] (bit-exact: k2 = g outer g) */
#define WIDX(k) ((k) < 6 ? (k) : 10 - (k))

extern __shared__ float2 smem_dyn[];

__global__ __launch_bounds__(NTHREADS, 4)
void ssim_main(const float* __restrict__ x, const float* __restrict__ y,
               const float* __restrict__ kern, float* __restrict__ out) {
    float2* s_v1 = smem_dyn;                 // [TH][S2] (sx,sy)
    float2* s_v2 = s_v1 + TH * S2;           // [TH][S2] (sxx,syy)
    float*  s_v3 = (float*)(s_v2 + TH * S2); // [TH][S2] sxy

    const int tid = threadIdx.x;
    const int lane = tid & 31;
    const int plane = blockIdx.z;            // 64 = 32 batch * 2 chan (NCHW)
    const int ch = plane & 1;
    const int oh0 = blockIdx.y * TH;
    const int ow0 = blockIdx.x * TW;
    const float* xp = x + (size_t)plane * IMG * IMG;
    const float* yp = y + (size_t)plane * IMG * IMG;

    // ---- weights per warp (no barrier): lanes 0-10 row sums, 11-21 col sums ----
    float s = 0.f;
    {
        const float* kc = kern + ch * KS * KS;
        if (lane < 22) {
            const float* base = (lane < KS) ? (kc + lane * KS) : (kc + (lane - KS));
            int stride = (lane < KS) ? 1 : KS;
            #pragma unroll
            for (int j = 0; j < KS; j++) s += __ldg(base + j * stride);
        }
    }
    float T = (lane < KS) ? s : 0.f;
    #pragma unroll
    for (int o = 16; o > 0; o >>= 1) T += __shfl_xor_sync(0xffffffffu, T, o);
    const float invT = 1.0f / T;

    u64 wv2[6];
    #pragma unroll
    for (int k = 0; k < 6; k++) {
        float w = __shfl_sync(0xffffffffu, s, k);
        wv2[k] = pack2(w, w);
    }

    // ---- stage 1: vertical conv straight from global (uniform predicated) ----
    for (int t = tid; t < NTASK; t += NTHREADS) {
        int rgi = t / COLS;
        int col = t - rgi * COLS;
        int rg = rgi * RG;
        int gc = ow0 + col - HALO;
        bool colok = (unsigned)gc < (unsigned)IMG;
        int r0 = oh0 + rg - HALO;
        const float* xb = xp + (ptrdiff_t)r0 * IMG + gc;
        const float* yb = yp + (ptrdiff_t)r0 * IMG + gc;

        u64 a1[RG], a2[RG]; float a3[RG];
        #pragma unroll
        for (int i = 0; i < RG; i++) { a1[i] = 0ull; a2[i] = 0ull; a3[i] = 0.f; }

        #pragma unroll
        for (int tt = 0; tt < RG + KS - 1; tt++) {   // 14 input rows
            int gr = r0 + tt;
            float vx = 0.f, vy = 0.f;
            if (colok && (unsigned)gr < (unsigned)IMG) {
                vx = __ldg(xb + tt * IMG);
                vy = __ldg(yb + tt * IMG);
            }
            u64 u = pack2(vx, vy);
            u64 v = mul2(u, u);
            float pxy = vx * vy;
            #pragma unroll
            for (int i = 0; i < RG; i++) {
                int k = tt - i;
                if (k >= 0 && k < KS) {
                    int wi = WIDX(k);
                    a1[i] = fma2(wv2[wi], u, a1[i]);
                    a2[i] = fma2(wv2[wi], v, a2[i]);
                    a3[i] = fmaf(__uint_as_float((unsigned)(wv2[wi] & 0xffffffffull)), pxy, a3[i]);
                }
            }
        }
        #pragma unroll
        for (int i = 0; i < RG; i++) {
            *reinterpret_cast<u64*>(&s_v1[(rg + i) * S2 + col]) = a1[i];
            *reinterpret_cast<u64*>(&s_v2[(rg + i) * S2 + col]) = a2[i];
            s_v3[(rg + i) * S2 + col] = a3[i];
        }
    }

    __syncthreads();

    // ---- stage-2 weights: re-derive by shuffle (s, invT kept live, +2 regs only) ----
    u64 wh2[6]; float whs[6];
    #pragma unroll
    for (int k = 0; k < 6; k++) {
        float w = __shfl_sync(0xffffffffu, s, KS + k) * invT;
        whs[k] = w; wh2[k] = pack2(w, w);
    }

    // ---- stage 2: horizontal conv, two half-tasks of 4 px ----
    const int row = lane;          // lanes span rows -> odd stride, conflict-free
    const int c0 = (tid >> 5) * 8;
    const float C1 = 1e-4f, C2 = 9e-4f;
    float lsum = 0.f;

    #pragma unroll
    for (int ph = 0; ph < 2; ph++) {
        int cb = c0 + 4 * ph;
        u64 h1[4], h2[4]; float h3[4];
        #pragma unroll
        for (int p = 0; p < 4; p++) { h1[p] = 0ull; h2[p] = 0ull; h3[p] = 0.f; }

        #pragma unroll
        for (int j = 0; j < RG + KS - 1; j++) {      // 14 input cols
            u64 b1 = *reinterpret_cast<const u64*>(&s_v1[row * S2 + cb + j]);
            u64 b2 = *reinterpret_cast<const u64*>(&s_v2[row * S2 + cb + j]);
            float b3 = s_v3[row * S2 + cb + j];
            #pragma unroll
            for (int p = 0; p < 4; p++) {
                int k = j - p;
                if (k >= 0 && k < KS) {
                    int wi = WIDX(k);
                    h1[p] = fma2(wh2[wi], b1, h1[p]);
                    h2[p] = fma2(wh2[wi], b2, h2[p]);
                    h3[p] = fmaf(whs[wi], b3, h3[p]);
                }
            }
        }
        #pragma unroll
        for (int p = 0; p < 4; p++) {
            float mux, muy; unpack2(h1[p], mux, muy);
            float ex2, ey2; unpack2(h2[p], ex2, ey2);
            float exy = h3[p];
            float mux2 = mux * mux, muy2 = muy * muy, muxy = mux * muy;
            float sx = ex2 - mux2, sy = ey2 - muy2, sxy = exy - muxy;
            float num = (2.f * muxy + C1) * (2.f * sxy + C2);
            float den = (mux2 + muy2 + C1) * (sx + sy + C2);
            lsum += __fdividef(num, den);
        }
    }

    // ---- reduction: warp -> block -> slotted global atomic -> last-block finalize ----
    #pragma unroll
    for (int o = 16; o > 0; o >>= 1) lsum += __shfl_xor_sync(0xffffffffu, lsum, o);
    __shared__ float wsum[NTHREADS / 32];
    __shared__ unsigned s_last;
    if (lane == 0) wsum[tid >> 5] = lsum;
    __syncthreads();
    if (tid == 0) {
        float b = 0.f;
        #pragma unroll
        for (int w = 0; w < NTHREADS / 32; w++) b += wsum[w];
        atomicAdd(&g_slots[blockIdx.y * 8 + blockIdx.x], (double)b);
        __threadfence();
        unsigned prev = atomicAdd(&g_done, 1u);
        s_last = (prev == (unsigned)(NBLK - 1)) ? 1u : 0u;
    }
    __syncthreads();

    if (s_last) {
        __threadfence();
        if (tid < NSLOTS) {
            double v = __ldcg(&g_slots[tid]);    // L2-coherent read of atomic results
            g_slots[tid] = 0.0;                  // reset for next graph replay
            #pragma unroll
            for (int o = 16; o > 0; o >>= 1) v += __shfl_xor_sync(0xffffffffu, v, o);
            __shared__ double dsum[4];
            if (lane == 0) dsum[tid >> 5] = v;
            __syncthreads();
            if (tid == 0) {
                double total = dsum[0] + dsum[1] + dsum[2] + dsum[3];
                out[0] = 1.0f - (float)(total * (1.0 / (32.0 * 2.0 * 512.0 * 512.0)));
                g_done = 0;                      // reset counter for next replay
            }
        }
    }
}

extern "C" void kernel_launch(void* const* d_in, const int* in_sizes, int n_in,
                              void* d_out, int out_size) {
    const float* x = (const float*)d_in[0];
    const float* y = (const float*)d_in[1];
    const float* kern = (const float*)d_in[2];
    float* out = (float*)d_out;

    dim3 grid(IMG / TW, IMG / TH, 64);
    ssim_main<<<grid, NTHREADS, SMEM_BYTES>>>(x, y, kern, out);
}

// round 6
// speedup vs baseline: 1.1276x; 1.1276x over previous
#include <cuda_runtime.h>

#define IMG 512
#define TW 64
#define TH 32
#define KS 11
#define HALO 5
#define COLS 74              /* TW + 2*HALO */
#define S2 75                /* float2 row stride (odd -> conflict-free) */
#define NP 37                /* u64 row stride for paired xy plane (odd) */
#define RG 4                 /* output rows per vertical task */
#define NTASK (COLS*(TH/RG)) /* 592 */
#define NTHREADS 256
/* smem: s_v1 32*75*8 + s_v2 32*75*8 + s_p3 32*37*8 = 47872 -> 4 CTAs/SM */
#define SMEM_BYTES (TH*S2*8*2 + TH*NP*8)

typedef unsigned long long u64;

__device__ double g_accum;
__device__ float g_wv[2][KS];
__device__ float g_wh[2][KS];

__device__ __forceinline__ u64 pack2(float x, float y) {
    u64 r; asm("mov.b64 %0, {%1,%2};" : "=l"(r) : "f"(x), "f"(y)); return r;
}
__device__ __forceinline__ void unpack2(u64 v, float& x, float& y) {
    asm("mov.b64 {%0,%1}, %2;" : "=f"(x), "=f"(y) : "l"(v));
}
__device__ __forceinline__ u64 fma2(u64 a, u64 b, u64 c) {
    u64 d; asm("fma.rn.f32x2 %0, %1, %2, %3;" : "=l"(d) : "l"(a), "l"(b), "l"(c)); return d;
}
__device__ __forceinline__ u64 mul2(u64 a, u64 b) {
    u64 d; asm("mul.rn.f32x2 %0, %1, %2;" : "=l"(d) : "l"(a), "l"(b)); return d;
}

/* Gaussian symmetry w[k] == w[10-k] (bit-exact: k2 = g outer g) */
#define WIDX(k) ((k) < 6 ? (k) : 10 - (k))

// Rank-1 factor reconstruction, parallel: warp 0 -> ch 0, warp 1 -> ch 1.
__global__ void prep_kernel(const float* __restrict__ kern) {
    int tid = threadIdx.x;
    if (tid == 0) g_accum = 0.0;
    if (tid < 64) {
        int ch = tid >> 5, lane = tid & 31;
        const float* kc = kern + ch * KS * KS;
        float s = 0.f;
        if (lane < KS) {
            #pragma unroll
            for (int j = 0; j < KS; j++) s += kc[lane * KS + j];       // row sums
        } else if (lane < 2 * KS) {
            #pragma unroll
            for (int j = 0; j < KS; j++) s += kc[j * KS + lane - KS];  // col sums
        }
        float contrib = (lane < KS) ? s : 0.f;
        #pragma unroll
        for (int o = 16; o > 0; o >>= 1) contrib += __shfl_xor_sync(0xffffffffu, contrib, o);
        if (lane < KS)           g_wv[ch][lane] = s;
        else if (lane < 2 * KS)  g_wh[ch][lane - KS] = s / contrib;
    }
}

extern __shared__ float2 smem_dyn[];

/* accumulate one input row (vx,vy) into RG row accumulators */
__device__ __forceinline__ void vaccum(float vx, float vy, int tt,
                                       const u64* __restrict__ wv2,
                                       u64* a1, u64* a2, float* a3) {
    u64 u = pack2(vx, vy);
    u64 v = mul2(u, u);
    float pxy = vx * vy;
    #pragma unroll
    for (int i = 0; i < RG; i++) {
        int k = tt - i;
        if (k >= 0 && k < KS) {
            int wi = WIDX(k);
            a1[i] = fma2(wv2[wi], u, a1[i]);
            a2[i] = fma2(wv2[wi], v, a2[i]);
            a3[i] = fmaf(__uint_as_float((unsigned)(wv2[wi] & 0xffffffffull)), pxy, a3[i]);
        }
    }
}

__global__ __launch_bounds__(NTHREADS, 4)
void ssim_main(const float* __restrict__ x, const float* __restrict__ y) {
    float2* s_v1 = smem_dyn;                  // [TH][S2] (sx,sy)
    float2* s_v2 = s_v1 + TH * S2;            // [TH][S2] (sxx,syy)
    float2* s_p3 = s_v2 + TH * S2;            // [TH][NP] sxy column-paired
    float*  s_p3f = (float*)s_p3;             // 32-bit view, row stride 2*NP = 74

    const int tid = threadIdx.x;
    const int plane = blockIdx.z;             // 64 = 32 batch * 2 chan (NCHW)
    const int ch = plane & 1;
    const int oh0 = blockIdx.y * TH;
    const int ow0 = blockIdx.x * TW;
    const float* xp = x + (size_t)plane * IMG * IMG;
    const float* yp = y + (size_t)plane * IMG * IMG;

    u64 wv2[6];
    #pragma unroll
    for (int k = 0; k < 6; k++) { float w = __ldg(&g_wv[ch][k]); wv2[k] = pack2(w, w); }

    // block-uniform interior test (tile + halo fully inside image)
    const bool interior = (blockIdx.x >= 1) & (blockIdx.x <= 6) &
                          (blockIdx.y >= 1) & (blockIdx.y <= 14);

    // ---- stage 1: vertical conv straight from global ----
    if (interior) {
        for (int t = tid; t < NTASK; t += NTHREADS) {
            int rgi = t / COLS;
            int col = t - rgi * COLS;
            int rg = rgi * RG;
            int r0 = oh0 + rg - HALO;
            const float* xb = xp + (ptrdiff_t)r0 * IMG + (ow0 + col - HALO);
            const float* yb = yp + (ptrdiff_t)r0 * IMG + (ow0 + col - HALO);

            u64 a1[RG], a2[RG]; float a3[RG];
            #pragma unroll
            for (int i = 0; i < RG; i++) { a1[i] = 0ull; a2[i] = 0ull; a3[i] = 0.f; }

            #pragma unroll
            for (int tt = 0; tt < RG + KS - 1; tt++)   // 14 rows, unpredicated
                vaccum(__ldg(xb + tt * IMG), __ldg(yb + tt * IMG), tt, wv2, a1, a2, a3);

            #pragma unroll
            for (int i = 0; i < RG; i++) {
                *reinterpret_cast<u64*>(&s_v1[(rg + i) * S2 + col]) = a1[i];
                *reinterpret_cast<u64*>(&s_v2[(rg + i) * S2 + col]) = a2[i];
                s_p3f[(rg + i) * (2 * NP) + col] = a3[i];
            }
        }
    } else {
        for (int t = tid; t < NTASK; t += NTHREADS) {
            int rgi = t / COLS;
            int col = t - rgi * COLS;
            int rg = rgi * RG;
            int gc = ow0 + col - HALO;
            bool colok = (unsigned)gc < (unsigned)IMG;
            int r0 = oh0 + rg - HALO;
            const float* xb = xp + (ptrdiff_t)r0 * IMG + gc;
            const float* yb = yp + (ptrdiff_t)r0 * IMG + gc;

            u64 a1[RG], a2[RG]; float a3[RG];
            #pragma unroll
            for (int i = 0; i < RG; i++) { a1[i] = 0ull; a2[i] = 0ull; a3[i] = 0.f; }

            #pragma unroll
            for (int tt = 0; tt < RG + KS - 1; tt++) {
                int gr = r0 + tt;
                float vx = 0.f, vy = 0.f;
                if (colok && (unsigned)gr < (unsigned)IMG) {
                    vx = __ldg(xb + tt * IMG);
                    vy = __ldg(yb + tt * IMG);
                }
                vaccum(vx, vy, tt, wv2, a1, a2, a3);
            }
            #pragma unroll
            for (int i = 0; i < RG; i++) {
                *reinterpret_cast<u64*>(&s_v1[(rg + i) * S2 + col]) = a1[i];
                *reinterpret_cast<u64*>(&s_v2[(rg + i) * S2 + col]) = a2[i];
                s_p3f[(rg + i) * (2 * NP) + col] = a3[i];
            }
        }
    }

    __syncthreads();

    // ---- stage 2: horizontal conv, two half-tasks of 4 px ----
    u64 wh2[6]; float whs[6];
    #pragma unroll
    for (int k = 0; k < 6; k++) { float w = __ldg(&g_wh[ch][k]); whs[k] = w; wh2[k] = pack2(w, w); }

    const int row = tid & 31;      // lanes span rows -> odd strides, conflict-free
    const int c0 = (tid >> 5) * 8;
    const float C1 = 1e-4f, C2 = 9e-4f;
    float lsum = 0.f;

    #pragma unroll
    for (int ph = 0; ph < 2; ph++) {
        int cb = c0 + 4 * ph;          // even
        int cw = cb >> 1;              // u64 word base in paired plane
        u64 h1[4], h2[4]; float h3[4];
        #pragma unroll
        for (int p = 0; p < 4; p++) { h1[p] = 0ull; h2[p] = 0ull; h3[p] = 0.f; }

        float2 pw;
        #pragma unroll
        for (int j = 0; j < RG + KS - 1; j++) {      // 14 input cols
            u64 b1 = *reinterpret_cast<const u64*>(&s_v1[row * S2 + cb + j]);
            u64 b2 = *reinterpret_cast<const u64*>(&s_v2[row * S2 + cb + j]);
            float b3;
            if ((j & 1) == 0) { pw = s_p3[row * NP + cw + (j >> 1)]; b3 = pw.x; }
            else              { b3 = pw.y; }
            #pragma unroll
            for (int p = 0; p < 4; p++) {
                int k = j - p;
                if (k >= 0 && k < KS) {
                    int wi = WIDX(k);
                    h1[p] = fma2(wh2[wi], b1, h1[p]);
                    h2[p] = fma2(wh2[wi], b2, h2[p]);
                    h3[p] = fmaf(whs[wi], b3, h3[p]);
                }
            }
        }
        #pragma unroll
        for (int p = 0; p < 4; p++) {
            float mux, muy; unpack2(h1[p], mux, muy);
            float ex2, ey2; unpack2(h2[p], ex2, ey2);
            float exy = h3[p];
            float muxy = mux * muy;
            float sxy  = fmaf(-mux, muy, exy);                   // exy - mux*muy
            float na   = fmaf(muxy, 2.0f, C1);                   // imm-FFMA
            float nb   = fmaf(sxy,  2.0f, C2);                   // imm-FFMA
            float dena = fmaf(mux, mux, fmaf(muy, muy, C1));     // mux2+muy2+C1
            float sx   = fmaf(-mux, mux, ex2);
            float sy   = fmaf(-muy, muy, ey2);
            float denb = (sx + sy) + C2;
            lsum += __fdividef(na * nb, dena * denb);
        }
    }

    // ---- reduction: warp -> block -> one double atomic ----
    #pragma unroll
    for (int o = 16; o > 0; o >>= 1) lsum += __shfl_xor_sync(0xffffffffu, lsum, o);
    __shared__ float wsum[NTHREADS / 32];
    if ((tid & 31) == 0) wsum[tid >> 5] = lsum;
    __syncthreads();
    if (tid == 0) {
        float b = 0.f;
        #pragma unroll
        for (int w = 0; w < NTHREADS / 32; w++) b += wsum[w];
        atomicAdd(&g_accum, (double)b);
    }
}

__global__ void finalize_kernel(float* __restrict__ out) {
    if (threadIdx.x == 0) {
        out[0] = 1.0f - (float)(g_accum * (1.0 / (32.0 * 2.0 * 512.0 * 512.0)));
    }
}

extern "C" void kernel_launch(void* const* d_in, const int* in_sizes, int n_in,
                              void* d_out, int out_size) {
    const float* x = (const float*)d_in[0];
    const float* y = (const float*)d_in[1];
    const float* kern = (const float*)d_in[2];
    float* out = (float*)d_out;

    prep_kernel<<<1, 64>>>(kern);
    dim3 grid(IMG / TW, IMG / TH, 64);
    ssim_main<<<grid, NTHREADS, SMEM_BYTES>>>(x, y);
    finalize_kernel<<<1, 32>>>(out);
}

// round 7
// speedup vs baseline: 1.2344x; 1.0947x over previous
#include <cuda_runtime.h>

#define IMG 512
#define TW 64
#define TH 32
#define KS 11
#define HALO 5
#define COLS 74              /* TW + 2*HALO */
#define S2 75                /* float2 row stride (odd -> conflict-free) */
#define RG 4                 /* output rows per vertical task */
#define NTASK (COLS*(TH/RG)) /* 592 */
#define NTHREADS 256
/* smem: s_v1 32*75*8 + s_vq 32*75*8 = 38400 B */
#define SMEM_BYTES (TH*S2*8*2)

typedef unsigned long long u64;

__device__ double g_accum;
__device__ float g_wv[2][KS];
__device__ float g_wh[2][KS];

__device__ __forceinline__ u64 pack2(float x, float y) {
    u64 r; asm("mov.b64 %0, {%1,%2};" : "=l"(r) : "f"(x), "f"(y)); return r;
}
__device__ __forceinline__ void unpack2(u64 v, float& x, float& y) {
    asm("mov.b64 {%0,%1}, %2;" : "=f"(x), "=f"(y) : "l"(v));
}
__device__ __forceinline__ u64 fma2(u64 a, u64 b, u64 c) {
    u64 d; asm("fma.rn.f32x2 %0, %1, %2, %3;" : "=l"(d) : "l"(a), "l"(b), "l"(c)); return d;
}

/* Gaussian symmetry w[k] == w[10-k] (bit-exact: k2 = g outer g) */
#define WIDX(k) ((k) < 6 ? (k) : 10 - (k))

// Rank-1 factor reconstruction, parallel: warp 0 -> ch 0, warp 1 -> ch 1.
__global__ void prep_kernel(const float* __restrict__ kern) {
    int tid = threadIdx.x;
    if (tid == 0) g_accum = 0.0;
    if (tid < 64) {
        int ch = tid >> 5, lane = tid & 31;
        const float* kc = kern + ch * KS * KS;
        float s = 0.f;
        if (lane < KS) {
            #pragma unroll
            for (int j = 0; j < KS; j++) s += kc[lane * KS + j];       // row sums
        } else if (lane < 2 * KS) {
            #pragma unroll
            for (int j = 0; j < KS; j++) s += kc[j * KS + lane - KS];  // col sums
        }
        float contrib = (lane < KS) ? s : 0.f;
        #pragma unroll
        for (int o = 16; o > 0; o >>= 1) contrib += __shfl_xor_sync(0xffffffffu, contrib, o);
        if (lane < KS)           g_wv[ch][lane] = s;
        else if (lane < 2 * KS)  g_wh[ch][lane - KS] = s / contrib;
    }
}

extern __shared__ float2 smem_dyn[];

/* accumulate one input px (vx,vy) into RG row accumulators:
   stream u = (x, y), stream q = (x^2 + y^2, x*y) */
__device__ __forceinline__ void vaccum(float vx, float vy, int tt,
                                       const u64* __restrict__ wv2,
                                       u64* a1, u64* aq) {
    u64 u = pack2(vx, vy);
    float s2  = fmaf(vy, vy, vx * vx);
    float pxy = vx * vy;
    u64 q = pack2(s2, pxy);
    #pragma unroll
    for (int i = 0; i < RG; i++) {
        int k = tt - i;
        if (k >= 0 && k < KS) {
            int wi = WIDX(k);
            a1[i] = fma2(wv2[wi], u, a1[i]);
            aq[i] = fma2(wv2[wi], q, aq[i]);
        }
    }
}

__global__ __launch_bounds__(NTHREADS, 4)
void ssim_main(const float* __restrict__ x, const float* __restrict__ y) {
    float2* s_v1 = smem_dyn;                  // [TH][S2] (sum_x, sum_y)
    float2* s_vq = s_v1 + TH * S2;            // [TH][S2] (sum_{x^2+y^2}, sum_xy)

    const int tid = threadIdx.x;
    const int plane = blockIdx.z;             // 64 = 32 batch * 2 chan (NCHW)
    const int ch = plane & 1;
    const int oh0 = blockIdx.y * TH;
    const int ow0 = blockIdx.x * TW;
    const float* xp = x + (size_t)plane * IMG * IMG;
    const float* yp = y + (size_t)plane * IMG * IMG;

    u64 wv2[6];
    #pragma unroll
    for (int k = 0; k < 6; k++) { float w = __ldg(&g_wv[ch][k]); wv2[k] = pack2(w, w); }

    // block-uniform interior test (tile + halo fully inside image)
    const bool interior = (blockIdx.x >= 1) & (blockIdx.x <= 6) &
                          (blockIdx.y >= 1) & (blockIdx.y <= 14);

    // ---- stage 1: vertical conv straight from global ----
    if (interior) {
        for (int t = tid; t < NTASK; t += NTHREADS) {
            int rgi = t / COLS;
            int col = t - rgi * COLS;
            int rg = rgi * RG;
            int r0 = oh0 + rg - HALO;
            const float* xb = xp + (ptrdiff_t)r0 * IMG + (ow0 + col - HALO);
            const float* yb = yp + (ptrdiff_t)r0 * IMG + (ow0 + col - HALO);

            u64 a1[RG], aq[RG];
            #pragma unroll
            for (int i = 0; i < RG; i++) { a1[i] = 0ull; aq[i] = 0ull; }

            #pragma unroll
            for (int tt = 0; tt < RG + KS - 1; tt++)   // 14 rows, unpredicated
                vaccum(__ldg(xb + tt * IMG), __ldg(yb + tt * IMG), tt, wv2, a1, aq);

            #pragma unroll
            for (int i = 0; i < RG; i++) {
                *reinterpret_cast<u64*>(&s_v1[(rg + i) * S2 + col]) = a1[i];
                *reinterpret_cast<u64*>(&s_vq[(rg + i) * S2 + col]) = aq[i];
            }
        }
    } else {
        for (int t = tid; t < NTASK; t += NTHREADS) {
            int rgi = t / COLS;
            int col = t - rgi * COLS;
            int rg = rgi * RG;
            int gc = ow0 + col - HALO;
            bool colok = (unsigned)gc < (unsigned)IMG;
            int r0 = oh0 + rg - HALO;
            const float* xb = xp + (ptrdiff_t)r0 * IMG + gc;
            const float* yb = yp + (ptrdiff_t)r0 * IMG + gc;

            u64 a1[RG], aq[RG];
            #pragma unroll
            for (int i = 0; i < RG; i++) { a1[i] = 0ull; aq[i] = 0ull; }

            #pragma unroll
            for (int tt = 0; tt < RG + KS - 1; tt++) {
                int gr = r0 + tt;
                float vx = 0.f, vy = 0.f;
                if (colok && (unsigned)gr < (unsigned)IMG) {
                    vx = __ldg(xb + tt * IMG);
                    vy = __ldg(yb + tt * IMG);
                }
                vaccum(vx, vy, tt, wv2, a1, aq);
            }
            #pragma unroll
            for (int i = 0; i < RG; i++) {
                *reinterpret_cast<u64*>(&s_v1[(rg + i) * S2 + col]) = a1[i];
                *reinterpret_cast<u64*>(&s_vq[(rg + i) * S2 + col]) = aq[i];
            }
        }
    }

    __syncthreads();

    // ---- stage 2: horizontal conv, single 8-px pass per thread ----
    u64 wh2[6];
    #pragma unroll
    for (int k = 0; k < 6; k++) { float w = __ldg(&g_wh[ch][k]); wh2[k] = pack2(w, w); }

    const int row = tid & 31;      // lanes span rows -> odd stride, conflict-free
    const int c0 = (tid >> 5) * 8;
    const float C1 = 1e-4f, C2 = 9e-4f;
    float lsum = 0.f;

    u64 h1[8], hq[8];
    #pragma unroll
    for (int p = 0; p < 8; p++) { h1[p] = 0ull; hq[p] = 0ull; }

    #pragma unroll
    for (int j = 0; j < 8 + KS - 1; j++) {      // 18 input cols (shared across all 8 px)
        u64 b1 = *reinterpret_cast<const u64*>(&s_v1[row * S2 + c0 + j]);
        u64 bq = *reinterpret_cast<const u64*>(&s_vq[row * S2 + c0 + j]);
        #pragma unroll
        for (int p = 0; p < 8; p++) {
            int k = j - p;
            if (k >= 0 && k < KS) {
                int wi = WIDX(k);
                h1[p] = fma2(wh2[wi], b1, h1[p]);
                hq[p] = fma2(wh2[wi], bq, hq[p]);
            }
        }
    }

    // ---- epilogue: SSIM per pixel ----
    #pragma unroll
    for (int p = 0; p < 8; p++) {
        float mux, muy; unpack2(h1[p], mux, muy);
        float es, exy;  unpack2(hq[p], es, exy);     // es = E[x^2+y^2]
        float muxy = mux * muy;
        float sxy  = fmaf(-mux, muy, exy);           // E[xy] - mux*muy
        float na   = fmaf(muxy, 2.0f, C1);
        float nb   = fmaf(sxy,  2.0f, C2);
        float m2   = fmaf(mux, mux, muy * muy);      // mux^2 + muy^2
        float dena = m2 + C1;
        float denb = (es - m2) + C2;                 // (sx + sy) + C2
        lsum += __fdividef(na * nb, dena * denb);
    }

    // ---- reduction: warp -> block -> one double atomic ----
    #pragma unroll
    for (int o = 16; o > 0; o >>= 1) lsum += __shfl_xor_sync(0xffffffffu, lsum, o);
    __shared__ float wsum[NTHREADS / 32];
    if ((tid & 31) == 0) wsum[tid >> 5] = lsum;
    __syncthreads();
    if (tid == 0) {
        float b = 0.f;
        #pragma unroll
        for (int w = 0; w < NTHREADS / 32; w++) b += wsum[w];
        atomicAdd(&g_accum, (double)b);
    }
}

__global__ void finalize_kernel(float* __restrict__ out) {
    if (threadIdx.x == 0) {
        out[0] = 1.0f - (float)(g_accum * (1.0 / (32.0 * 2.0 * 512.0 * 512.0)));
    }
}

extern "C" void kernel_launch(void* const* d_in, const int* in_sizes, int n_in,
                              void* d_out, int out_size) {
    const float* x = (const float*)d_in[0];
    const float* y = (const float*)d_in[1];
    const float* kern = (const float*)d_in[2];
    float* out = (float*)d_out;

    prep_kernel<<<1, 64>>>(kern);
    dim3 grid(IMG / TW, IMG / TH, 64);
    ssim_main<<<grid, NTHREADS, SMEM_BYTES>>>(x, y);
    finalize_kernel<<<1, 32>>>(out);
}

// round 8
// speedup vs baseline: 1.3513x; 1.0947x over previous
#include <cuda_runtime.h>

#define IMG 512
#define TW 64
#define TH 32
#define KS 11
#define HALO 5
#define COLS 74              /* TW + 2*HALO */
#define S2 75                /* float2 row stride (odd -> conflict-free) */
#define RG 8                 /* output rows per vertical task */
#define NROWS (RG + KS - 1)  /* 18 input rows per task */
#define NTASK (COLS*(TH/RG)) /* 296 */
#define NTHREADS 256
/* smem: s_v1 32*75*8 + s_vq 32*75*8 = 38400 B */
#define SMEM_BYTES (TH*S2*8*2)

typedef unsigned long long u64;

__device__ double g_accum;
__device__ float g_wv[2][KS];
__device__ float g_wh[2][KS];

__device__ __forceinline__ u64 pack2(float x, float y) {
    u64 r; asm("mov.b64 %0, {%1,%2};" : "=l"(r) : "f"(x), "f"(y)); return r;
}
__device__ __forceinline__ void unpack2(u64 v, float& x, float& y) {
    asm("mov.b64 {%0,%1}, %2;" : "=f"(x), "=f"(y) : "l"(v));
}
__device__ __forceinline__ u64 fma2(u64 a, u64 b, u64 c) {
    u64 d; asm("fma.rn.f32x2 %0, %1, %2, %3;" : "=l"(d) : "l"(a), "l"(b), "l"(c)); return d;
}

/* Gaussian symmetry w[k] == w[10-k] (bit-exact: k2 = g outer g) */
#define WIDX(k) ((k) < 6 ? (k) : 10 - (k))

// Rank-1 factor reconstruction, parallel: warp 0 -> ch 0, warp 1 -> ch 1.
__global__ void prep_kernel(const float* __restrict__ kern) {
    int tid = threadIdx.x;
    if (tid == 0) g_accum = 0.0;
    if (tid < 64) {
        int ch = tid >> 5, lane = tid & 31;
        const float* kc = kern + ch * KS * KS;
        float s = 0.f;
        if (lane < KS) {
            #pragma unroll
            for (int j = 0; j < KS; j++) s += kc[lane * KS + j];       // row sums
        } else if (lane < 2 * KS) {
            #pragma unroll
            for (int j = 0; j < KS; j++) s += kc[j * KS + lane - KS];  // col sums
        }
        float contrib = (lane < KS) ? s : 0.f;
        #pragma unroll
        for (int o = 16; o > 0; o >>= 1) contrib += __shfl_xor_sync(0xffffffffu, contrib, o);
        if (lane < KS)           g_wv[ch][lane] = s;
        else if (lane < 2 * KS)  g_wh[ch][lane - KS] = s / contrib;
    }
}

extern __shared__ float2 smem_dyn[];

/* accumulate one input px (vx,vy) into RG row accumulators:
   stream u = (x, y), stream q = (x^2 + y^2, x*y) */
__device__ __forceinline__ void vaccum(float vx, float vy, int tt,
                                       const u64* __restrict__ wv2,
                                       u64* a1, u64* aq) {
    u64 u = pack2(vx, vy);
    float s2  = fmaf(vy, vy, vx * vx);
    float pxy = vx * vy;
    u64 q = pack2(s2, pxy);
    #pragma unroll
    for (int i = 0; i < RG; i++) {
        int k = tt - i;
        if (k >= 0 && k < KS) {
            int wi = WIDX(k);
            a1[i] = fma2(wv2[wi], u, a1[i]);
            aq[i] = fma2(wv2[wi], q, aq[i]);
        }
    }
}

__global__ __launch_bounds__(NTHREADS, 4)
void ssim_main(const float* __restrict__ x, const float* __restrict__ y) {
    float2* s_v1 = smem_dyn;                  // [TH][S2] (sum_x, sum_y)
    float2* s_vq = s_v1 + TH * S2;            // [TH][S2] (sum_{x^2+y^2}, sum_xy)

    const int tid = threadIdx.x;
    const int plane = blockIdx.z;             // 64 = 32 batch * 2 chan (NCHW)
    const int ch = plane & 1;
    const int oh0 = blockIdx.y * TH;
    const int ow0 = blockIdx.x * TW;
    const float* xp = x + (size_t)plane * IMG * IMG;
    const float* yp = y + (size_t)plane * IMG * IMG;

    u64 wv2[6];
    #pragma unroll
    for (int k = 0; k < 6; k++) { float w = __ldg(&g_wv[ch][k]); wv2[k] = pack2(w, w); }

    // block-uniform interior test (tile + halo fully inside image)
    const bool interior = (blockIdx.x >= 1) & (blockIdx.x <= 6) &
                          (blockIdx.y >= 1) & (blockIdx.y <= 14);

    // ---- stage 1: vertical conv straight from global ----
    if (interior) {
        for (int t = tid; t < NTASK; t += NTHREADS) {
            int rgi = t / COLS;
            int col = t - rgi * COLS;
            int rg = rgi * RG;
            int r0 = oh0 + rg - HALO;
            const float* xb = xp + (ptrdiff_t)r0 * IMG + (ow0 + col - HALO);
            const float* yb = yp + (ptrdiff_t)r0 * IMG + (ow0 + col - HALO);

            u64 a1[RG], aq[RG];
            #pragma unroll
            for (int i = 0; i < RG; i++) { a1[i] = 0ull; aq[i] = 0ull; }

            #pragma unroll
            for (int tt = 0; tt < NROWS; tt++)   // 18 rows, unpredicated
                vaccum(__ldg(xb + tt * IMG), __ldg(yb + tt * IMG), tt, wv2, a1, aq);

            #pragma unroll
            for (int i = 0; i < RG; i++) {
                *reinterpret_cast<u64*>(&s_v1[(rg + i) * S2 + col]) = a1[i];
                *reinterpret_cast<u64*>(&s_vq[(rg + i) * S2 + col]) = aq[i];
            }
        }
    } else {
        for (int t = tid; t < NTASK; t += NTHREADS) {
            int rgi = t / COLS;
            int col = t - rgi * COLS;
            int rg = rgi * RG;
            int gc = ow0 + col - HALO;
            bool colok = (unsigned)gc < (unsigned)IMG;
            int r0 = oh0 + rg - HALO;
            const float* xb = xp + (ptrdiff_t)r0 * IMG + gc;
            const float* yb = yp + (ptrdiff_t)r0 * IMG + gc;

            u64 a1[RG], aq[RG];
            #pragma unroll
            for (int i = 0; i < RG; i++) { a1[i] = 0ull; aq[i] = 0ull; }

            #pragma unroll
            for (int tt = 0; tt < NROWS; tt++) {
                int gr = r0 + tt;
                float vx = 0.f, vy = 0.f;
                if (colok && (unsigned)gr < (unsigned)IMG) {
                    vx = __ldg(xb + tt * IMG);
                    vy = __ldg(yb + tt * IMG);
                }
                vaccum(vx, vy, tt, wv2, a1, aq);
            }
            #pragma unroll
            for (int i = 0; i < RG; i++) {
                *reinterpret_cast<u64*>(&s_v1[(rg + i) * S2 + col]) = a1[i];
                *reinterpret_cast<u64*>(&s_vq[(rg + i) * S2 + col]) = aq[i];
            }
        }
    }

    __syncthreads();

    // ---- stage 2: horizontal conv, single 8-px pass per thread ----
    u64 wh2[6];
    #pragma unroll
    for (int k = 0; k < 6; k++) { float w = __ldg(&g_wh[ch][k]); wh2[k] = pack2(w, w); }

    const int row = tid & 31;      // lanes span rows -> odd stride, conflict-free
    const int c0 = (tid >> 5) * 8;
    const float C1 = 1e-4f, C2 = 9e-4f;
    float lsum = 0.f;

    u64 h1[8], hq[8];
    #pragma unroll
    for (int p = 0; p < 8; p++) { h1[p] = 0ull; hq[p] = 0ull; }

    #pragma unroll
    for (int j = 0; j < 8 + KS - 1; j++) {      // 18 input cols (shared across all 8 px)
        u64 b1 = *reinterpret_cast<const u64*>(&s_v1[row * S2 + c0 + j]);
        u64 bq = *reinterpret_cast<const u64*>(&s_vq[row * S2 + c0 + j]);
        #pragma unroll
        for (int p = 0; p < 8; p++) {
            int k = j - p;
            if (k >= 0 && k < KS) {
                int wi = WIDX(k);
                h1[p] = fma2(wh2[wi], b1, h1[p]);
                hq[p] = fma2(wh2[wi], bq, hq[p]);
            }
        }
    }

    // ---- epilogue: SSIM per pixel ----
    #pragma unroll
    for (int p = 0; p < 8; p++) {
        float mux, muy; unpack2(h1[p], mux, muy);
        float es, exy;  unpack2(hq[p], es, exy);     // es = E[x^2+y^2]
        float muxy = mux * muy;
        float sxy  = fmaf(-mux, muy, exy);           // E[xy] - mux*muy
        float na   = fmaf(muxy, 2.0f, C1);
        float nb   = fmaf(sxy,  2.0f, C2);
        float m2   = fmaf(mux, mux, muy * muy);      // mux^2 + muy^2
        float dena = m2 + C1;
        float denb = (es - m2) + C2;                 // (sx + sy) + C2
        lsum += __fdividef(na * nb, dena * denb);
    }

    // ---- reduction: warp -> block -> one double atomic ----
    #pragma unroll
    for (int o = 16; o > 0; o >>= 1) lsum += __shfl_xor_sync(0xffffffffu, lsum, o);
    __shared__ float wsum[NTHREADS / 32];
    if ((tid & 31) == 0) wsum[tid >> 5] = lsum;
    __syncthreads();
    if (tid == 0) {
        float b = 0.f;
        #pragma unroll
        for (int w = 0; w < NTHREADS / 32; w++) b += wsum[w];
        atomicAdd(&g_accum, (double)b);
    }
}

__global__ void finalize_kernel(float* __restrict__ out) {
    if (threadIdx.x == 0) {
        out[0] = 1.0f - (float)(g_accum * (1.0 / (32.0 * 2.0 * 512.0 * 512.0)));
    }
}

extern "C" void kernel_launch(void* const* d_in, const int* in_sizes, int n_in,
                              void* d_out, int out_size) {
    const float* x = (const float*)d_in[0];
    const float* y = (const float*)d_in[1];
    const float* kern = (const float*)d_in[2];
    float* out = (float*)d_out;

    prep_kernel<<<1, 64>>>(kern);
    dim3 grid(IMG / TW, IMG / TH, 64);
    ssim_main<<<grid, NTHREADS, SMEM_BYTES>>>(x, y);
    finalize_kernel<<<1, 32>>>(out);
}